// round 5
// baseline (speedup 1.0000x reference)
#include <cuda_runtime.h>
#include <cuda_bf16.h>
#include <cstdint>

// ---------------- constants ----------------
#define NROWS   8192
#define NHALF   4096
#define DIM     128
#define NT      64            // 128-row tiles
#define NTILES  2080          // upper triangle incl diag
#define QS      127.0f        // int8 quant scale

// dequant+temperature fold: exp(2*dot/(127^2)) = 2^(dot * S); magic-number int->float
#define IMAGIC  0x4B400000
#define SCALE_S ((float)(2.8853900817779268 / (127.0 * 127.0)))
#define SCALE_C ((float)(-12582912.0 * (2.8853900817779268 / (127.0 * 127.0))))

// dynamic smem: A tile @0 (16KB), B tile @16384 (16KB)
#define SM_A 0
#define SM_B 16384
#define SM_TOTAL 32768

// ---------------- device scratch ----------------
__device__ uint32_t g_repsq[NROWS * 32];        // int8 quantized rows, 4 elems/word
__device__ float    g_posT[NHALF];              // exact fp32 positives / T
__device__ float    g_partial[NROWS * NT];      // [row][other-tile], one writer per slot
__device__ float    g_blocksum[1024];
__device__ unsigned g_ticket;                   // zero-init; reset by last block

// ---------------- helpers ----------------
__device__ __forceinline__ float ex2f(float x) {
    float y; asm("ex2.approx.f32 %0, %1;" : "=f"(y) : "f"(x)); return y;
}
__device__ __forceinline__ uint32_t smem_u32(const void* p) {
    uint32_t a;
    asm("{ .reg .u64 t; cvta.to.shared.u64 t, %1; cvt.u32.u64 %0, t; }" : "=r"(a) : "l"(p));
    return a;
}
__device__ __forceinline__ void ldsm4(uint32_t* r, uint32_t addr) {
    asm volatile("ldmatrix.sync.aligned.m8n8.x4.shared.b16 {%0,%1,%2,%3}, [%4];"
        : "=r"(r[0]), "=r"(r[1]), "=r"(r[2]), "=r"(r[3]) : "r"(addr));
}
__device__ __forceinline__ void imma16832(int* c, const uint32_t* a, uint32_t b0, uint32_t b1) {
    asm volatile(
        "mma.sync.aligned.m16n8k32.row.col.s32.s8.s8.s32 "
        "{%0,%1,%2,%3}, {%4,%5,%6,%7}, {%8,%9}, {%0,%1,%2,%3};\n"
        : "+r"(c[0]), "+r"(c[1]), "+r"(c[2]), "+r"(c[3])
        : "r"(a[0]), "r"(a[1]), "r"(a[2]), "r"(a[3]), "r"(b0), "r"(b1));
}
__device__ __forceinline__ int q8(float v) {
    int q = __float2int_rn(v);
    return max(-127, min(127, q));
}

// ---------------- kernel 1: fused normalize + positives + int8 quantize ----------------
__global__ void normpos_kernel(const float* __restrict__ p1, const float* __restrict__ p2) {
    int i    = blockIdx.x * 8 + (threadIdx.x >> 5);
    int lane = threadIdx.x & 31;
    float4 a = ((const float4*)(p1 + (size_t)i * DIM))[lane];
    float4 b = ((const float4*)(p2 + (size_t)i * DIM))[lane];
    float sa  = a.x * a.x + a.y * a.y + a.z * a.z + a.w * a.w;
    float sb  = b.x * b.x + b.y * b.y + b.z * b.z + b.w * b.w;
    float sab = a.x * b.x + a.y * b.y + a.z * b.z + a.w * b.w;
#pragma unroll
    for (int o = 16; o > 0; o >>= 1) {
        sa  += __shfl_xor_sync(0xffffffffu, sa, o);
        sb  += __shfl_xor_sync(0xffffffffu, sb, o);
        sab += __shfl_xor_sync(0xffffffffu, sab, o);
    }
    float na = fmaxf(sqrtf(sa), 1e-12f), nb = fmaxf(sqrtf(sb), 1e-12f);
    float ia = QS / na, ib = QS / nb;
    if (lane == 0) g_posT[i] = 2.0f * sab / (na * nb);
    int qa0 = q8(a.x * ia), qa1 = q8(a.y * ia), qa2 = q8(a.z * ia), qa3 = q8(a.w * ia);
    int qb0 = q8(b.x * ib), qb1 = q8(b.y * ib), qb2 = q8(b.z * ib), qb3 = q8(b.w * ib);
    uint32_t ua = (uint32_t)(qa0 & 0xFF) | ((uint32_t)(qa1 & 0xFF) << 8)
                | ((uint32_t)(qa2 & 0xFF) << 16) | ((uint32_t)qa3 << 24);
    uint32_t ub = (uint32_t)(qb0 & 0xFF) | ((uint32_t)(qb1 & 0xFF) << 8)
                | ((uint32_t)(qb2 & 0xFF) << 16) | ((uint32_t)qb3 << 24);
    g_repsq[(size_t)i * 32 + lane] = ua;
    g_repsq[(size_t)(i + NHALF) * 32 + lane] = ub;
}

// ---------------- kernel 2: IMMA tile + exp + row/col sums ----------------
// 2080 CTAs (one upper-triangle 128x128 tile), 256 threads (8 warps, 4 wm x 2 wn).
__global__ __launch_bounds__(256, 2) void sim_kernel() {
    extern __shared__ char smc[];
    uint32_t smem = smem_u32(smc);
    __shared__ float rowpart[2][128];
    __shared__ float colpart[4][128];

    int tid  = threadIdx.x;
    int warp = tid >> 5, lane = tid & 31;
    int wm = warp >> 1, wn = warp & 1;
    int gid = lane >> 2, t4 = lane & 3;

    // decode upper-triangle pair (ti <= tj)
    int b = blockIdx.x;
    int ti = (int)((129.0f - sqrtf(16641.0f - 8.0f * (float)b)) * 0.5f);
#define FROW(t) ((t) * NT - (t) * ((t) - 1) / 2)
    while (FROW(ti + 1) <= b) ti++;
    while (FROW(ti) > b) ti--;
    int tj = ti + (b - FROW(ti));
    int i0 = ti * 128, j0 = tj * 128;
    bool isdiag = (ti == tj);

    // load tiles: coalesced LDG.128, XOR-swizzled STS.128 (row=128B, 8 chunks of 16B)
    {
        const uint4* ga = (const uint4*)(g_repsq + (size_t)i0 * 32);
#pragma unroll
        for (int it = 0; it < 4; it++) {
            int idx = tid + it * 256;               // 0..1023
            int r = idx >> 3, c16 = idx & 7;
            *(uint4*)(smc + SM_A + r * 128 + ((c16 ^ (r & 7)) << 4)) = ga[idx];
        }
        if (!isdiag) {
            const uint4* gb = (const uint4*)(g_repsq + (size_t)j0 * 32);
#pragma unroll
            for (int it = 0; it < 4; it++) {
                int idx = tid + it * 256;
                int r = idx >> 3, c16 = idx & 7;
                *(uint4*)(smc + SM_B + r * 128 + ((c16 ^ (r & 7)) << 4)) = gb[idx];
            }
        }
    }
    __syncthreads();
    uint32_t smB = smem + (isdiag ? SM_A : SM_B);

    // A ldmatrix bases: lanes 0-15 -> rows, chunk-lo; lanes 16-31 -> rows, chunk-hi
    int rl = lane & 15, sA = lane >> 4;
    uint32_t baseA[2]; int kxA[2];
#pragma unroll
    for (int mf = 0; mf < 2; mf++) {
        int row = wm * 32 + mf * 16 + rl;
        int rx = row & 7;
        baseA[mf] = smem + SM_A + (uint32_t)row * 128 + (uint32_t)((sA ^ (rx & 1)) << 4);
        kxA[mf] = rx >> 1;
    }
    // B ldmatrix bases: lanes 0-7 cols0-7 lo, 8-15 cols0-7 hi, 16-23 cols8-15 lo, 24-31 hi
    int coll = (lane & 7) | ((lane >> 4) << 3);
    int sB = (lane >> 3) & 1;
    uint32_t baseB[4]; int kxB[4];
#pragma unroll
    for (int np = 0; np < 4; np++) {
        int col = wn * 64 + np * 16 + coll;
        int cx = col & 7;
        baseB[np] = smB + (uint32_t)col * 128 + (uint32_t)((sB ^ (cx & 1)) << 4);
        kxB[np] = cx >> 1;
    }

    int acc[2][8][4];
#pragma unroll
    for (int mf = 0; mf < 2; mf++)
#pragma unroll
        for (int nf = 0; nf < 8; nf++)
#pragma unroll
            for (int q = 0; q < 4; q++) acc[mf][nf][q] = 0;

#pragma unroll
    for (int k = 0; k < 4; k++) {     // 4 k32 steps over K=128
        uint32_t a[2][4], bq[4][4];
#pragma unroll
        for (int mf = 0; mf < 2; mf++)
            ldsm4(a[mf], baseA[mf] + (uint32_t)((k ^ kxA[mf]) << 5));
#pragma unroll
        for (int np = 0; np < 4; np++)
            ldsm4(bq[np], baseB[np] + (uint32_t)((k ^ kxB[np]) << 5));
#pragma unroll
        for (int nf = 0; nf < 8; nf++) {
            uint32_t b0 = bq[nf >> 1][(nf & 1) * 2];
            uint32_t b1 = bq[nf >> 1][(nf & 1) * 2 + 1];
#pragma unroll
            for (int mf = 0; mf < 2; mf++)
                imma16832(acc[mf][nf], a[mf], b0, b1);
        }
    }

    // epilogue: magic int->float + FFMA dequant + ex2; diag masked; row + col sums
    float rs[2][2] = {{0.f, 0.f}, {0.f, 0.f}};
    float cs[8][2];
#pragma unroll
    for (int nf = 0; nf < 8; nf++) { cs[nf][0] = 0.f; cs[nf][1] = 0.f; }

#pragma unroll
    for (int mf = 0; mf < 2; mf++)
#pragma unroll
        for (int h = 0; h < 2; h++) {
            int rowg = i0 + wm * 32 + mf * 16 + h * 8 + gid;
            float ssum = 0.f;
#pragma unroll
            for (int nf = 0; nf < 8; nf++) {
                int colg = j0 + wn * 64 + nf * 8 + t4 * 2;
                float f0 = __int_as_float(acc[mf][nf][h * 2]     + IMAGIC);
                float f1 = __int_as_float(acc[mf][nf][h * 2 + 1] + IMAGIC);
                float e0 = ex2f(fmaf(f0, SCALE_S, SCALE_C));
                float e1 = ex2f(fmaf(f1, SCALE_S, SCALE_C));
                if (isdiag) {
                    if (rowg == colg)     e0 = 0.f;
                    if (rowg == colg + 1) e1 = 0.f;
                }
                ssum += e0 + e1;
                cs[nf][0] += e0;
                cs[nf][1] += e1;
            }
            rs[mf][h] += ssum;
        }

    // row sums: quad-reduce, per-wn halves into smem
#pragma unroll
    for (int mf = 0; mf < 2; mf++)
#pragma unroll
        for (int h = 0; h < 2; h++) {
            float v = rs[mf][h];
            v += __shfl_xor_sync(0xffffffffu, v, 1);
            v += __shfl_xor_sync(0xffffffffu, v, 2);
            if (t4 == 0)
                rowpart[wn][wm * 32 + mf * 16 + h * 8 + gid] = v;
        }

    // col sums (off-diag only): reduce across gid lanes
    if (!isdiag) {
#pragma unroll
        for (int nf = 0; nf < 8; nf++)
#pragma unroll
            for (int c = 0; c < 2; c++) {
                float u = cs[nf][c];
                u += __shfl_xor_sync(0xffffffffu, u, 4);
                u += __shfl_xor_sync(0xffffffffu, u, 8);
                u += __shfl_xor_sync(0xffffffffu, u, 16);
                if (gid == 0)
                    colpart[wm][wn * 64 + nf * 8 + t4 * 2 + c] = u;
            }
    }
    __syncthreads();

    if (tid < 128) {
        float rv = rowpart[0][tid] + rowpart[1][tid];
        g_partial[(size_t)(i0 + tid) * NT + tj] = rv;
        if (!isdiag) {
            float cv = colpart[0][tid] + colpart[1][tid] + colpart[2][tid] + colpart[3][tid];
            g_partial[(size_t)(j0 + tid) * NT + ti] = cv;
        }
    }
}

// ---------------- kernel 3: fused finalize (last-block pattern) ----------------
__global__ void finalize_kernel(float* __restrict__ out) {
    __shared__ float part[8];
    __shared__ float red[256];
    __shared__ int lastflag;
    int tid = threadIdx.x;
    int w = tid >> 5, lane = tid & 31;
    int r = blockIdx.x * 8 + w;
    float2 v = ((const float2*)(g_partial + (size_t)r * NT))[lane];
    float d = v.x + v.y;
#pragma unroll
    for (int o = 16; o > 0; o >>= 1) d += __shfl_xor_sync(0xffffffffu, d, o);
    if (lane == 0) part[w] = logf(d) - g_posT[r & (NHALF - 1)];
    __syncthreads();
    if (tid == 0) {
        float ssum = 0.f;
#pragma unroll
        for (int k = 0; k < 8; k++) ssum += part[k];
        g_blocksum[blockIdx.x] = ssum;
        __threadfence();
        unsigned t = atomicAdd(&g_ticket, 1u);
        lastflag = (t == 1023u);
    }
    __syncthreads();
    if (lastflag) {
        float a = g_blocksum[tid] + g_blocksum[tid + 256]
                + g_blocksum[tid + 512] + g_blocksum[tid + 768];
        red[tid] = a;
        __syncthreads();
        for (int sft = 128; sft > 0; sft >>= 1) {
            if (tid < sft) red[tid] += red[tid + sft];
            __syncthreads();
        }
        if (tid == 0) {
            out[0] = red[0] / (float)NROWS;
            g_ticket = 0u;    // reset for next graph replay
        }
    }
}

// ---------------- launch ----------------
extern "C" void kernel_launch(void* const* d_in, const int* in_sizes, int n_in,
                              void* d_out, int out_size) {
    const float* p1 = (const float*)d_in[0];
    const float* p2 = (const float*)d_in[1];
    float* out = (float*)d_out;

    cudaFuncSetAttribute(sim_kernel, cudaFuncAttributeMaxDynamicSharedMemorySize, SM_TOTAL);

    normpos_kernel<<<NHALF / 8, 256>>>(p1, p2);
    sim_kernel<<<NTILES, 256, SM_TOTAL>>>();
    finalize_kernel<<<NROWS / 8, 256>>>(out);
}

// round 6
// speedup vs baseline: 2.4118x; 2.4118x over previous
#include <cuda_runtime.h>
#include <cuda_fp16.h>
#include <cstdint>

// ---------------- constants ----------------
#define NROWS   8192
#define NHALF   4096
#define DIM     128
#define NT      64            // 128-row tiles
#define NTILES  2080          // upper triangle incl diag
#define SQRT_L2T 1.6986436f   // sqrt(2/ln2); (s*a)·(s*b) = (2/ln2)*sim -> ex2 direct

// dynamic smem: A tile @0 (32KB), B tile @32768 (32KB)
#define SM_A 0
#define SM_B 32768
#define SM_TOTAL 65536

// ---------------- device scratch ----------------
__device__ __half   g_repsh[NROWS * DIM];       // normalized * SQRT_L2T, fp16
__device__ float    g_posT[NHALF];              // exact fp32 positives / T
__device__ float    g_partial[NROWS * NT];      // [row][other-tile], one writer per slot
__device__ float    g_blocksum[1024];
__device__ unsigned g_ticket;                   // zero-init; reset by last block each run

// ---------------- helpers ----------------
__device__ __forceinline__ float ex2f(float x) {
    float y; asm("ex2.approx.f32 %0, %1;" : "=f"(y) : "f"(x)); return y;
}
__device__ __forceinline__ uint32_t smem_u32(const void* p) {
    uint32_t a;
    asm("{ .reg .u64 t; cvta.to.shared.u64 t, %1; cvt.u32.u64 %0, t; }" : "=r"(a) : "l"(p));
    return a;
}
__device__ __forceinline__ void ldsm4(uint32_t* r, uint32_t addr) {
    asm volatile("ldmatrix.sync.aligned.m8n8.x4.shared.b16 {%0,%1,%2,%3}, [%4];"
        : "=r"(r[0]), "=r"(r[1]), "=r"(r[2]), "=r"(r[3]) : "r"(addr));
}
// f16 x f16 -> f16 accumulate: C/D packed as 2x b32 (4 halves)
__device__ __forceinline__ void hmma16816(uint32_t* c, const uint32_t* a, uint32_t b0, uint32_t b1) {
    asm volatile(
        "mma.sync.aligned.m16n8k16.row.col.f16.f16.f16.f16 "
        "{%0,%1}, {%2,%3,%4,%5}, {%6,%7}, {%0,%1};\n"
        : "+r"(c[0]), "+r"(c[1])
        : "r"(a[0]), "r"(a[1]), "r"(a[2]), "r"(a[3]), "r"(b0), "r"(b1));
}
// swizzled byte offset of (row, 16B-chunk) in a 128x256B tile: chunk ^ (row&7)
__device__ __forceinline__ uint32_t sw_off(int r, int c16) {
    return (uint32_t)r * 256 + (uint32_t)(c16 ^ (r & 7)) * 16;
}

// ---------------- kernel 1: fused normalize + positives + fp16 convert ----------------
__global__ void normpos_kernel(const float* __restrict__ p1, const float* __restrict__ p2) {
    int i    = blockIdx.x * 8 + (threadIdx.x >> 5);
    int lane = threadIdx.x & 31;
    float4 a = ((const float4*)(p1 + (size_t)i * DIM))[lane];
    float4 b = ((const float4*)(p2 + (size_t)i * DIM))[lane];
    float sa  = a.x * a.x + a.y * a.y + a.z * a.z + a.w * a.w;
    float sb  = b.x * b.x + b.y * b.y + b.z * b.z + b.w * b.w;
    float sab = a.x * b.x + a.y * b.y + a.z * b.z + a.w * b.w;
#pragma unroll
    for (int o = 16; o > 0; o >>= 1) {
        sa  += __shfl_xor_sync(0xffffffffu, sa, o);
        sb  += __shfl_xor_sync(0xffffffffu, sb, o);
        sab += __shfl_xor_sync(0xffffffffu, sab, o);
    }
    float na = fmaxf(sqrtf(sa), 1e-12f), nb = fmaxf(sqrtf(sb), 1e-12f);
    float ia = SQRT_L2T / na, ib = SQRT_L2T / nb;
    if (lane == 0) g_posT[i] = 2.0f * sab / (na * nb);
    __half2 a0 = __floats2half2_rn(a.x * ia, a.y * ia);
    __half2 a1 = __floats2half2_rn(a.z * ia, a.w * ia);
    __half2 b0 = __floats2half2_rn(b.x * ib, b.y * ib);
    __half2 b1 = __floats2half2_rn(b.z * ib, b.w * ib);
    uint2 ua, ub;
    ua.x = *(uint32_t*)&a0; ua.y = *(uint32_t*)&a1;
    ub.x = *(uint32_t*)&b0; ub.y = *(uint32_t*)&b1;
    ((uint2*)(g_repsh + (size_t)i * DIM))[lane] = ua;
    ((uint2*)(g_repsh + (size_t)(i + NHALF) * DIM))[lane] = ub;
}

// ---------------- kernel 2: HMMA(f16 acc) tile + exp + row/col sums ----------------
// 2080 CTAs (one upper-triangle 128x128 tile), 256 threads (8 warps, 4 wm x 2 wn).
__global__ __launch_bounds__(256, 2) void sim_kernel() {
    extern __shared__ char smc[];
    uint32_t smem = smem_u32(smc);
    __shared__ float rowpart[2][128];
    __shared__ float colpart[4][128];

    int tid  = threadIdx.x;
    int warp = tid >> 5, lane = tid & 31;
    int wm = warp >> 1, wn = warp & 1;
    int gid = lane >> 2, t4 = lane & 3;

    // decode upper-triangle pair (ti <= tj)
    int b = blockIdx.x;
    int ti = (int)((129.0f - sqrtf(16641.0f - 8.0f * (float)b)) * 0.5f);
#define FROW(t) ((t) * NT - (t) * ((t) - 1) / 2)
    while (FROW(ti + 1) <= b) ti++;
    while (FROW(ti) > b) ti--;
    int tj = ti + (b - FROW(ti));
    int i0 = ti * 128, j0 = tj * 128;
    bool isdiag = (ti == tj);

    // load tiles: coalesced LDG.128, XOR-swizzled STS.128
    {
        const uint4* ga = (const uint4*)(g_repsh + (size_t)i0 * DIM);
#pragma unroll
        for (int it = 0; it < 8; it++) {
            int idx = tid + it * 256;               // 0..2047
            int r = idx >> 4, c16 = idx & 15;
            *(uint4*)(smc + SM_A + sw_off(r, c16)) = ga[idx];
        }
        if (!isdiag) {
            const uint4* gb = (const uint4*)(g_repsh + (size_t)j0 * DIM);
#pragma unroll
            for (int it = 0; it < 8; it++) {
                int idx = tid + it * 256;
                int r = idx >> 4, c16 = idx & 15;
                *(uint4*)(smc + SM_B + sw_off(r, c16)) = gb[idx];
            }
        }
    }
    __syncthreads();
    uint32_t smB = smem + (isdiag ? SM_A : SM_B);

    // ldmatrix bases (identical to validated R4 bf16 layout)
    int rl = lane & 15, s = lane >> 4;
    uint32_t baseA[2], baseB[4];
    int kxA[2], kxB[4];
#pragma unroll
    for (int mf = 0; mf < 2; mf++) {
        int row = wm * 32 + mf * 16 + rl;
        int rx = row & 7;
        baseA[mf] = smem + SM_A + (uint32_t)row * 256 + (uint32_t)(s ^ (rx & 1)) * 16;
        kxA[mf] = rx >> 1;
    }
#pragma unroll
    for (int np = 0; np < 4; np++) {
        int row = wn * 64 + np * 16 + rl;
        int rx = row & 7;
        baseB[np] = smB + (uint32_t)row * 256 + (uint32_t)(s ^ (rx & 1)) * 16;
        kxB[np] = rx >> 1;
    }

    uint32_t acc[2][8][2];   // f16x2 accumulators
#pragma unroll
    for (int mf = 0; mf < 2; mf++)
#pragma unroll
        for (int nf = 0; nf < 8; nf++) { acc[mf][nf][0] = 0u; acc[mf][nf][1] = 0u; }

#pragma unroll
    for (int k = 0; k < 8; k++) {
        uint32_t a[2][4], bf[4][4];
#pragma unroll
        for (int mf = 0; mf < 2; mf++)
            ldsm4(a[mf], baseA[mf] + (uint32_t)((k ^ kxA[mf]) << 5));
#pragma unroll
        for (int np = 0; np < 4; np++)
            ldsm4(bf[np], baseB[np] + (uint32_t)((k ^ kxB[np]) << 5));
#pragma unroll
        for (int nf = 0; nf < 8; nf++) {
            uint32_t b0 = bf[nf >> 1][nf & 1];
            uint32_t b1 = bf[nf >> 1][(nf & 1) + 2];
#pragma unroll
            for (int mf = 0; mf < 2; mf++)
                hmma16816(acc[mf][nf], a[mf], b0, b1);
        }
    }

    // epilogue: unpack f16x2, ex2 (scale pre-folded); diag masked; row + col sums
    float rs[2][2] = {{0.f, 0.f}, {0.f, 0.f}};
    float cs[8][2];
#pragma unroll
    for (int nf = 0; nf < 8; nf++) { cs[nf][0] = 0.f; cs[nf][1] = 0.f; }

#pragma unroll
    for (int mf = 0; mf < 2; mf++)
#pragma unroll
        for (int h = 0; h < 2; h++) {    // h selects acc reg (rows h*8+gid)
            int rowg = i0 + wm * 32 + mf * 16 + h * 8 + gid;
            float ssum = 0.f;
#pragma unroll
            for (int nf = 0; nf < 8; nf++) {
                int colg = j0 + wn * 64 + nf * 8 + t4 * 2;
                float2 f = __half22float2(*(__half2*)&acc[mf][nf][h]);
                float e0 = ex2f(f.x);
                float e1 = ex2f(f.y);
                if (isdiag) {
                    if (rowg == colg)     e0 = 0.f;
                    if (rowg == colg + 1) e1 = 0.f;
                }
                ssum += e0 + e1;
                cs[nf][0] += e0;
                cs[nf][1] += e1;
            }
            rs[mf][h] += ssum;
        }

    // row sums: quad-reduce, per-wn halves into smem
#pragma unroll
    for (int mf = 0; mf < 2; mf++)
#pragma unroll
        for (int h = 0; h < 2; h++) {
            float v = rs[mf][h];
            v += __shfl_xor_sync(0xffffffffu, v, 1);
            v += __shfl_xor_sync(0xffffffffu, v, 2);
            if (t4 == 0)
                rowpart[wn][wm * 32 + mf * 16 + h * 8 + gid] = v;
        }

    // col sums (off-diag only): reduce across gid lanes
    if (!isdiag) {
#pragma unroll
        for (int nf = 0; nf < 8; nf++)
#pragma unroll
            for (int c = 0; c < 2; c++) {
                float u = cs[nf][c];
                u += __shfl_xor_sync(0xffffffffu, u, 4);
                u += __shfl_xor_sync(0xffffffffu, u, 8);
                u += __shfl_xor_sync(0xffffffffu, u, 16);
                if (gid == 0)
                    colpart[wm][wn * 64 + nf * 8 + t4 * 2 + c] = u;
            }
    }
    __syncthreads();

    if (tid < 128) {
        float rv = rowpart[0][tid] + rowpart[1][tid];
        g_partial[(size_t)(i0 + tid) * NT + tj] = rv;
        if (!isdiag) {
            float cv = colpart[0][tid] + colpart[1][tid] + colpart[2][tid] + colpart[3][tid];
            g_partial[(size_t)(j0 + tid) * NT + ti] = cv;
        }
    }
}

// ---------------- kernel 3: fused finalize (last-block pattern) ----------------
__global__ void finalize_kernel(float* __restrict__ out) {
    __shared__ float part[8];
    __shared__ float red[256];
    __shared__ int lastflag;
    int tid = threadIdx.x;
    int w = tid >> 5, lane = tid & 31;
    int r = blockIdx.x * 8 + w;
    float2 v = ((const float2*)(g_partial + (size_t)r * NT))[lane];
    float d = v.x + v.y;
#pragma unroll
    for (int o = 16; o > 0; o >>= 1) d += __shfl_xor_sync(0xffffffffu, d, o);
    if (lane == 0) part[w] = logf(d) - g_posT[r & (NHALF - 1)];
    __syncthreads();
    if (tid == 0) {
        float ssum = 0.f;
#pragma unroll
        for (int k = 0; k < 8; k++) ssum += part[k];
        g_blocksum[blockIdx.x] = ssum;
        __threadfence();
        unsigned t = atomicAdd(&g_ticket, 1u);
        lastflag = (t == 1023u);
    }
    __syncthreads();
    if (lastflag) {
        float a = g_blocksum[tid] + g_blocksum[tid + 256]
                + g_blocksum[tid + 512] + g_blocksum[tid + 768];
        red[tid] = a;
        __syncthreads();
        for (int sft = 128; sft > 0; sft >>= 1) {
            if (tid < sft) red[tid] += red[tid + sft];
            __syncthreads();
        }
        if (tid == 0) {
            out[0] = red[0] / (float)NROWS;
            g_ticket = 0u;    // reset for next graph replay
        }
    }
}

// ---------------- launch ----------------
extern "C" void kernel_launch(void* const* d_in, const int* in_sizes, int n_in,
                              void* d_out, int out_size) {
    const float* p1 = (const float*)d_in[0];
    const float* p2 = (const float*)d_in[1];
    float* out = (float*)d_out;

    cudaFuncSetAttribute(sim_kernel, cudaFuncAttributeMaxDynamicSharedMemorySize, SM_TOTAL);

    normpos_kernel<<<NHALF / 8, 256>>>(p1, p2);
    sim_kernel<<<NTILES, 256, SM_TOTAL>>>();
    finalize_kernel<<<NROWS / 8, 256>>>(out);
}

// round 7
// speedup vs baseline: 2.7840x; 1.1543x over previous
#include <cuda_runtime.h>
#include <cuda_fp16.h>
#include <cstdint>

// ---------------- constants ----------------
#define NROWS   8192
#define NHALF   4096
#define DIM     128
#define NT      64            // 128-row tiles
#define NTILES  2080          // upper triangle incl diag
#define SQRT_L2T 1.6986436f   // sqrt(2/ln2); (s*a)·(s*b) = (2/ln2)*sim -> ex2 direct

// dynamic smem: A tile @0 (32KB), B tile @32768 (32KB)
#define SM_A 0
#define SM_B 32768
#define SM_TOTAL 65536

// ---------------- device scratch ----------------
__device__ __half   g_repsh[NROWS * DIM];       // normalized * SQRT_L2T, fp16
__device__ float    g_posT[NHALF];              // exact fp32 positives / T
__device__ float    g_partial[NROWS * NT];      // [row][other-tile], one writer per slot
__device__ float    g_blocksum[1024];
__device__ unsigned g_ticket;                   // zero-init; reset by last block each run

// ---------------- helpers ----------------
__device__ __forceinline__ uint32_t h2ex2(uint32_t x) {
    uint32_t y; asm("ex2.approx.f16x2 %0, %1;" : "=r"(y) : "r"(x)); return y;
}
__device__ __forceinline__ uint32_t hadd2(uint32_t a, uint32_t b) {
    uint32_t c; asm("add.f16x2 %0, %1, %2;" : "=r"(c) : "r"(a), "r"(b)); return c;
}
__device__ __forceinline__ uint32_t smem_u32(const void* p) {
    uint32_t a;
    asm("{ .reg .u64 t; cvta.to.shared.u64 t, %1; cvt.u32.u64 %0, t; }" : "=r"(a) : "l"(p));
    return a;
}
__device__ __forceinline__ void ldsm4(uint32_t* r, uint32_t addr) {
    asm volatile("ldmatrix.sync.aligned.m8n8.x4.shared.b16 {%0,%1,%2,%3}, [%4];"
        : "=r"(r[0]), "=r"(r[1]), "=r"(r[2]), "=r"(r[3]) : "r"(addr));
}
// f16 x f16 -> f16 accumulate
__device__ __forceinline__ void hmma16816(uint32_t* c, const uint32_t* a, uint32_t b0, uint32_t b1) {
    asm volatile(
        "mma.sync.aligned.m16n8k16.row.col.f16.f16.f16.f16 "
        "{%0,%1}, {%2,%3,%4,%5}, {%6,%7}, {%0,%1};\n"
        : "+r"(c[0]), "+r"(c[1])
        : "r"(a[0]), "r"(a[1]), "r"(a[2]), "r"(a[3]), "r"(b0), "r"(b1));
}
// swizzled byte offset of (row, 16B-chunk) in a 128x256B tile: chunk ^ (row&7)
__device__ __forceinline__ uint32_t sw_off(int r, int c16) {
    return (uint32_t)r * 256 + (uint32_t)(c16 ^ (r & 7)) * 16;
}

// ---------------- kernel 1: normalize + positives + fp16, 2 pairs/warp (MLP=4) ----------------
__global__ void normpos_kernel(const float* __restrict__ p1, const float* __restrict__ p2) {
    int w    = blockIdx.x * 8 + (threadIdx.x >> 5);  // 0..2047
    int lane = threadIdx.x & 31;
    int i1 = w, i2 = w + 2048;
    float4 a1 = ((const float4*)(p1 + (size_t)i1 * DIM))[lane];
    float4 b1 = ((const float4*)(p2 + (size_t)i1 * DIM))[lane];
    float4 a2 = ((const float4*)(p1 + (size_t)i2 * DIM))[lane];
    float4 b2 = ((const float4*)(p2 + (size_t)i2 * DIM))[lane];
    float sa1 = a1.x*a1.x + a1.y*a1.y + a1.z*a1.z + a1.w*a1.w;
    float sb1 = b1.x*b1.x + b1.y*b1.y + b1.z*b1.z + b1.w*b1.w;
    float sc1 = a1.x*b1.x + a1.y*b1.y + a1.z*b1.z + a1.w*b1.w;
    float sa2 = a2.x*a2.x + a2.y*a2.y + a2.z*a2.z + a2.w*a2.w;
    float sb2 = b2.x*b2.x + b2.y*b2.y + b2.z*b2.z + b2.w*b2.w;
    float sc2 = a2.x*b2.x + a2.y*b2.y + a2.z*b2.z + a2.w*b2.w;
#pragma unroll
    for (int o = 16; o > 0; o >>= 1) {
        sa1 += __shfl_xor_sync(0xffffffffu, sa1, o);
        sb1 += __shfl_xor_sync(0xffffffffu, sb1, o);
        sc1 += __shfl_xor_sync(0xffffffffu, sc1, o);
        sa2 += __shfl_xor_sync(0xffffffffu, sa2, o);
        sb2 += __shfl_xor_sync(0xffffffffu, sb2, o);
        sc2 += __shfl_xor_sync(0xffffffffu, sc2, o);
    }
    float na1 = fmaxf(sqrtf(sa1), 1e-12f), nb1 = fmaxf(sqrtf(sb1), 1e-12f);
    float na2 = fmaxf(sqrtf(sa2), 1e-12f), nb2 = fmaxf(sqrtf(sb2), 1e-12f);
    if (lane == 0) {
        g_posT[i1] = 2.0f * sc1 / (na1 * nb1);
        g_posT[i2] = 2.0f * sc2 / (na2 * nb2);
    }
    float ia1 = SQRT_L2T / na1, ib1 = SQRT_L2T / nb1;
    float ia2 = SQRT_L2T / na2, ib2 = SQRT_L2T / nb2;
    uint2 u;
    __half2 h0, h1;
#define PACK_STORE(v, scale, row) \
    h0 = __floats2half2_rn((v).x * (scale), (v).y * (scale)); \
    h1 = __floats2half2_rn((v).z * (scale), (v).w * (scale)); \
    u.x = *(uint32_t*)&h0; u.y = *(uint32_t*)&h1; \
    ((uint2*)(g_repsh + (size_t)(row) * DIM))[lane] = u;
    PACK_STORE(a1, ia1, i1)
    PACK_STORE(b1, ib1, i1 + NHALF)
    PACK_STORE(a2, ia2, i2)
    PACK_STORE(b2, ib2, i2 + NHALF)
#undef PACK_STORE
}

// ---------------- kernel 2: HMMA tile + f16x2 exp + row/col sums ----------------
// 2080 CTAs (one upper-triangle 128x128 tile), 256 threads (8 warps, 4 wm x 2 wn).
__global__ __launch_bounds__(256, 3) void sim_kernel() {
    extern __shared__ char smc[];
    uint32_t smem = smem_u32(smc);
    __shared__ float rowpart[2][128];
    __shared__ float colpart[4][128];

    int tid  = threadIdx.x;
    int warp = tid >> 5, lane = tid & 31;
    int wm = warp >> 1, wn = warp & 1;
    int gid = lane >> 2, t4 = lane & 3;

    // decode upper-triangle pair (ti <= tj)
    int b = blockIdx.x;
    int ti = (int)((129.0f - sqrtf(16641.0f - 8.0f * (float)b)) * 0.5f);
#define FROW(t) ((t) * NT - (t) * ((t) - 1) / 2)
    while (FROW(ti + 1) <= b) ti++;
    while (FROW(ti) > b) ti--;
    int tj = ti + (b - FROW(ti));
    int i0 = ti * 128, j0 = tj * 128;
    bool isdiag = (ti == tj);

    // load tiles: coalesced LDG.128, XOR-swizzled STS.128
    {
        const uint4* ga = (const uint4*)(g_repsh + (size_t)i0 * DIM);
#pragma unroll
        for (int it = 0; it < 8; it++) {
            int idx = tid + it * 256;               // 0..2047
            int r = idx >> 4, c16 = idx & 15;
            *(uint4*)(smc + SM_A + sw_off(r, c16)) = ga[idx];
        }
        if (!isdiag) {
            const uint4* gb = (const uint4*)(g_repsh + (size_t)j0 * DIM);
#pragma unroll
            for (int it = 0; it < 8; it++) {
                int idx = tid + it * 256;
                int r = idx >> 4, c16 = idx & 15;
                *(uint4*)(smc + SM_B + sw_off(r, c16)) = gb[idx];
            }
        }
    }
    __syncthreads();
    uint32_t smB = smem + (isdiag ? SM_A : SM_B);

    // ldmatrix bases (validated layout)
    int rl = lane & 15, s = lane >> 4;
    uint32_t baseA[2], baseB[4];
    int kxA[2], kxB[4];
#pragma unroll
    for (int mf = 0; mf < 2; mf++) {
        int row = wm * 32 + mf * 16 + rl;
        int rx = row & 7;
        baseA[mf] = smem + SM_A + (uint32_t)row * 256 + (uint32_t)(s ^ (rx & 1)) * 16;
        kxA[mf] = rx >> 1;
    }
#pragma unroll
    for (int np = 0; np < 4; np++) {
        int row = wn * 64 + np * 16 + rl;
        int rx = row & 7;
        baseB[np] = smB + (uint32_t)row * 256 + (uint32_t)(s ^ (rx & 1)) * 16;
        kxB[np] = rx >> 1;
    }

    uint32_t acc[2][8][2];   // f16x2 accumulators
#pragma unroll
    for (int mf = 0; mf < 2; mf++)
#pragma unroll
        for (int nf = 0; nf < 8; nf++) { acc[mf][nf][0] = 0u; acc[mf][nf][1] = 0u; }

#pragma unroll
    for (int k = 0; k < 8; k++) {
        uint32_t a[2][4], bf[4][4];
#pragma unroll
        for (int mf = 0; mf < 2; mf++)
            ldsm4(a[mf], baseA[mf] + (uint32_t)((k ^ kxA[mf]) << 5));
#pragma unroll
        for (int np = 0; np < 4; np++)
            ldsm4(bf[np], baseB[np] + (uint32_t)((k ^ kxB[np]) << 5));
#pragma unroll
        for (int nf = 0; nf < 8; nf++) {
            uint32_t b0 = bf[nf >> 1][nf & 1];
            uint32_t b1 = bf[nf >> 1][(nf & 1) + 2];
#pragma unroll
            for (int mf = 0; mf < 2; mf++)
                hmma16816(acc[mf][nf], a[mf], b0, b1);
        }
    }

    // epilogue: packed f16x2 ex2 + HADD2 partials (bounded <=60, f16-safe)
    float rs[2][2];
    uint32_t csh[8];
#pragma unroll
    for (int nf = 0; nf < 8; nf++) csh[nf] = 0u;

#pragma unroll
    for (int mf = 0; mf < 2; mf++)
#pragma unroll
        for (int h = 0; h < 2; h++) {
            int rowg = i0 + wm * 32 + mf * 16 + h * 8 + gid;
            uint32_t rsh = 0u;
#pragma unroll
            for (int nf = 0; nf < 8; nf++) {
                uint32_t e = h2ex2(acc[mf][nf][h]);
                if (isdiag) {
                    int colg = j0 + wn * 64 + nf * 8 + t4 * 2;
                    if (rowg == colg)     e &= 0xFFFF0000u;   // zero lo half
                    if (rowg == colg + 1) e &= 0x0000FFFFu;   // zero hi half
                }
                rsh = hadd2(rsh, e);
                csh[nf] = hadd2(csh[nf], e);
            }
            float2 fr = __half22float2(*(__half2*)&rsh);
            rs[mf][h] = fr.x + fr.y;
        }

    // row sums: quad-reduce, per-wn halves into smem
#pragma unroll
    for (int mf = 0; mf < 2; mf++)
#pragma unroll
        for (int h = 0; h < 2; h++) {
            float v = rs[mf][h];
            v += __shfl_xor_sync(0xffffffffu, v, 1);
            v += __shfl_xor_sync(0xffffffffu, v, 2);
            if (t4 == 0)
                rowpart[wn][wm * 32 + mf * 16 + h * 8 + gid] = v;
        }

    // col sums (off-diag only): reduce across gid lanes
    if (!isdiag) {
#pragma unroll
        for (int nf = 0; nf < 8; nf++) {
            float2 fc = __half22float2(*(__half2*)&csh[nf]);
            float u0 = fc.x, u1 = fc.y;
#pragma unroll
            for (int o = 4; o <= 16; o <<= 1) {
                u0 += __shfl_xor_sync(0xffffffffu, u0, o);
                u1 += __shfl_xor_sync(0xffffffffu, u1, o);
            }
            if (gid == 0) {
                colpart[wm][wn * 64 + nf * 8 + t4 * 2]     = u0;
                colpart[wm][wn * 64 + nf * 8 + t4 * 2 + 1] = u1;
            }
        }
    }
    __syncthreads();

    if (tid < 128) {
        float rv = rowpart[0][tid] + rowpart[1][tid];
        g_partial[(size_t)(i0 + tid) * NT + tj] = rv;
        if (!isdiag) {
            float cv = colpart[0][tid] + colpart[1][tid] + colpart[2][tid] + colpart[3][tid];
            g_partial[(size_t)(j0 + tid) * NT + ti] = cv;
        }
    }
}

// ---------------- kernel 3: fused finalize (last-block pattern) ----------------
__global__ void finalize_kernel(float* __restrict__ out) {
    __shared__ float part[8];
    __shared__ float red[256];
    __shared__ int lastflag;
    int tid = threadIdx.x;
    int w = tid >> 5, lane = tid & 31;
    int r = blockIdx.x * 8 + w;
    float2 v = ((const float2*)(g_partial + (size_t)r * NT))[lane];
    float d = v.x + v.y;
#pragma unroll
    for (int o = 16; o > 0; o >>= 1) d += __shfl_xor_sync(0xffffffffu, d, o);
    if (lane == 0) part[w] = logf(d) - g_posT[r & (NHALF - 1)];
    __syncthreads();
    if (tid == 0) {
        float ssum = 0.f;
#pragma unroll
        for (int k = 0; k < 8; k++) ssum += part[k];
        g_blocksum[blockIdx.x] = ssum;
        __threadfence();
        unsigned t = atomicAdd(&g_ticket, 1u);
        lastflag = (t == 1023u);
    }
    __syncthreads();
    if (lastflag) {
        float a = g_blocksum[tid] + g_blocksum[tid + 256]
                + g_blocksum[tid + 512] + g_blocksum[tid + 768];
        red[tid] = a;
        __syncthreads();
        for (int sft = 128; sft > 0; sft >>= 1) {
            if (tid < sft) red[tid] += red[tid + sft];
            __syncthreads();
        }
        if (tid == 0) {
            out[0] = red[0] / (float)NROWS;
            g_ticket = 0u;    // reset for next graph replay
        }
    }
}

// ---------------- launch ----------------
extern "C" void kernel_launch(void* const* d_in, const int* in_sizes, int n_in,
                              void* d_out, int out_size) {
    const float* p1 = (const float*)d_in[0];
    const float* p2 = (const float*)d_in[1];
    float* out = (float*)d_out;

    cudaFuncSetAttribute(sim_kernel, cudaFuncAttributeMaxDynamicSharedMemorySize, SM_TOTAL);

    normpos_kernel<<<256, 256>>>(p1, p2);
    sim_kernel<<<NTILES, 256, SM_TOTAL>>>();
    finalize_kernel<<<NROWS / 8, 256>>>(out);
}